// round 3
// baseline (speedup 1.0000x reference)
#include <cuda_runtime.h>
#include <math.h>

#define Bc 4
#define Tt 288
#define Vv 512
#define Cc 32

// scratch (static __device__ arrays: allowed, no runtime allocation)
__device__ float g_comb[Bc * Cc * Tt * Vv];   // 75.5 MB
__device__ float g_cv[Bc * Tt * Vv];          // 2.36 MB
__device__ float g_imp[Bc * Tt];
__device__ float g_coef[Bc * 5];

// ---------------------------------------------------------------------------
// K0: impact scan (reverse decayed cumsum, summed over E with alpha), plus
// the event MLP -> sigmoid -> softmax -> per-batch expert coefs (ew_i / k_i).
// ---------------------------------------------------------------------------
__global__ void k0_small(const float* __restrict__ events,
                         const float* __restrict__ ef,
                         const float* __restrict__ w1,
                         const float* __restrict__ b1,
                         const float* __restrict__ w2,
                         const float* __restrict__ b2) {
    __shared__ float simp[Bc * Tt];
    __shared__ float sev[Bc * Tt * 3];
    int tid = threadIdx.x;

    for (int i = tid; i < Bc * Tt; i += blockDim.x) simp[i] = 0.f;
    for (int i = tid; i < Bc * Tt * 3; i += blockDim.x) sev[i] = events[i];
    __syncthreads();

    if (tid < 12) {
        int b = tid / 3, e = tid % 3;
        const float decay[3] = {300.f, 600.f, 180.f};
        const float alpha[3] = {0.3f, 0.5f, 0.2f};
        float r = expf(-1.f / decay[e]);
        float a = alpha[e];
        float s = 0.f;
        for (int t = Tt - 1; t >= 0; --t) {
            s = sev[(b * Tt + t) * 3 + e] + r * s;
            atomicAdd(&simp[b * Tt + t], a * s);
        }
    }

    if (tid < Bc) {
        int b = tid;
        float h[32];
#pragma unroll
        for (int j = 0; j < 32; ++j) {
            float acc = b1[j];
#pragma unroll
            for (int i = 0; i < 8; ++i) acc += ef[b * 8 + i] * w1[i * 32 + j];
            h[j] = fmaxf(acc, 0.f);
        }
        float lg[5];
#pragma unroll
        for (int k = 0; k < 5; ++k) {
            float acc = b2[k];
#pragma unroll
            for (int j = 0; j < 32; ++j) acc += h[j] * w2[j * 5 + k];
            lg[k] = 1.f / (1.f + expf(-acc));
        }
        float m = lg[0];
#pragma unroll
        for (int k = 1; k < 5; ++k) m = fmaxf(m, lg[k]);
        float ex[5];
        float ssum = 0.f;
#pragma unroll
        for (int k = 0; k < 5; ++k) { ex[k] = expf(lg[k] - m); ssum += ex[k]; }
        const float ks[5] = {3.f, 6.f, 12.f, 24.f, 48.f};
#pragma unroll
        for (int k = 0; k < 5; ++k) g_coef[b * 5 + k] = ex[k] / (ssum * ks[k]);
    }
    __syncthreads();
    for (int i = tid; i < Bc * Tt; i += blockDim.x) g_imp[i] = simp[i];
}

// ---------------------------------------------------------------------------
// Kcv: rolling mean / Bessel-corrected std over W=60, cv = std/(mean+1e-6),
// zero for t < 59. One thread per (b, v) column, streaming running sums.
// ---------------------------------------------------------------------------
__global__ void k_cv(const float* __restrict__ flow) {
    int g = blockIdx.x * blockDim.x + threadIdx.x;   // 0 .. B*V-1
    if (g >= Bc * Vv) return;
    int b = g >> 9;
    int v = g & (Vv - 1);
    const float* fp = flow + (size_t)b * Tt * Vv + v;
    float* cp = g_cv + (size_t)b * Tt * Vv + v;
    float s = 0.f, s2 = 0.f;
    for (int t = 0; t < Tt; ++t) {
        float f = fp[(size_t)t * Vv];
        s += f;
        s2 += f * f;
        if (t >= 60) {
            float fo = fp[(size_t)(t - 60) * Vv];
            s -= fo;
            s2 -= fo * fo;
        }
        float c = 0.f;
        if (t >= 59) {
            float mean = s * (1.f / 60.f);
            float var = (s2 - 60.f * mean * mean) * (1.f / 59.f);
            var = fmaxf(var, 0.f);
            c = sqrtf(var) / (mean + 1e-6f);
        }
        cp[(size_t)t * Vv] = c;
    }
}

// ---------------------------------------------------------------------------
// K1: event-weighted expert filter. For each (b,c,v) column, maintain 5
// sliding-window sums (k = 3,6,12,24,48, torch AvgPool2d padding semantics,
// count_include_pad) with a 64-deep smem ring buffer of x values.
// comb[t] = sum_i (ew_i / k_i) * S_i(t).   Window updates:
//   S(t) = S(t-1) + x[t - p + k - 1] - x[t - 1 - p],  p = k/2 (floor)
// Ring reads happen before the ring write of x[t+23]; start at t = -24 with
// zeroed ring so all window sums telescope correctly from empty state.
// ---------------------------------------------------------------------------
#define SL(i) ((((i) + 64) & 63) * 128 + tid)

__global__ void __launch_bounds__(128) k1_filter(const float* __restrict__ x) {
    __shared__ float rb[64 * 128];
    int tid = threadIdx.x;
    int col = blockIdx.x * 128 + tid;       // 0 .. B*C*V-1
    int v = col & (Vv - 1);
    int bc = col >> 9;                      // b*C + c
    int b = bc >> 5;
    const float* xp = x + (size_t)bc * Tt * Vv + v;
    float* cp = g_comb + (size_t)bc * Tt * Vv + v;

    float c0 = g_coef[b * 5 + 0];
    float c1 = g_coef[b * 5 + 1];
    float c2 = g_coef[b * 5 + 2];
    float c3 = g_coef[b * 5 + 3];
    float c4 = g_coef[b * 5 + 4];

#pragma unroll
    for (int s = 0; s < 64; ++s) rb[s * 128 + tid] = 0.f;

    float S0 = 0.f, S1 = 0.f, S2 = 0.f, S3 = 0.f, S4 = 0.f;

#pragma unroll 4
    for (int t = -24; t < Tt; ++t) {
        // reads first (ring slot for t+23 gets overwritten below)
        float a3  = rb[SL(t + 1)];
        float a6  = rb[SL(t + 2)];
        float a12 = rb[SL(t + 5)];
        float a24 = rb[SL(t + 11)];
        float d3  = rb[SL(t - 2)];
        float d6  = rb[SL(t - 4)];
        float d12 = rb[SL(t - 7)];
        float d24 = rb[SL(t - 13)];
        float d48 = rb[SL(t - 25)];

        int tin = t + 23;
        float xin = 0.f;
        if ((unsigned)tin < (unsigned)Tt) xin = __ldg(xp + (size_t)tin * Vv);

        S0 += a3  - d3;
        S1 += a6  - d6;
        S2 += a12 - d12;
        S3 += a24 - d24;
        S4 += xin - d48;

        rb[SL(tin)] = xin;

        if (t >= 0) {
            cp[(size_t)t * Vv] =
                c0 * S0 + c1 * S1 + c2 * S2 + c3 * S3 + c4 * S4;
        }
    }
}

// ---------------------------------------------------------------------------
// K2: fused channel mix + residual + CV modulation + impact.
// Block tile: one b, 4 t's, 32 v's (128 positions), all 32 output channels.
// GEMM: OUT[32 o][128 p] = W[32][64] * CAT[64][128], CAT = [x ; comb].
// Thread tile 4o x 4p; weights transposed in smem -> warp-broadcast LDS.128,
// cat loads are conflict-free LDS.128. Epilogue uses the x half of CAT as the
// residual, multiplies by (1+cv), adds impact, STG.128.
// ---------------------------------------------------------------------------
__global__ void __launch_bounds__(256) k2_mix(const float* __restrict__ x,
                                              const float* __restrict__ fw,
                                              const float* __restrict__ fb,
                                              float* __restrict__ out) {
    __shared__ float cat[64 * 128];   // [c][p], p = tl*32 + v
    __shared__ float wt[64 * 32];     // [c][o]  (transposed fusion_w)
    __shared__ float fbs[32];
    __shared__ float cvs[128];
    __shared__ float imps[4];

    int tid = threadIdx.x;
    int v0 = blockIdx.x * 32;
    int t0 = blockIdx.y * 4;
    int b  = blockIdx.z;

    // weights (transpose) + bias + cv tile + impact tile
    for (int i = tid; i < 2048; i += 256) {
        int o = i >> 6, c = i & 63;
        wt[c * 32 + o] = fw[i];
    }
    if (tid < 32) fbs[tid] = fb[tid];
    if (tid < 128) cvs[tid] = g_cv[(size_t)(b * Tt + t0 + (tid >> 5)) * Vv + v0 + (tid & 31)];
    if (tid < 4) imps[tid] = g_imp[b * Tt + t0 + tid];

    // load x tile and comb tile (float4, fully coalesced)
    const float4* x4 = reinterpret_cast<const float4*>(x);
    const float4* m4 = reinterpret_cast<const float4*>(g_comb);
    float4* cat4 = reinterpret_cast<float4*>(cat);
#pragma unroll
    for (int k = 0; k < 4; ++k) {
        int i = tid + k * 256;            // 0..1023
        int c = i >> 5;                   // 0..31
        int r = i & 31;                   // tl*8 + vq
        int tl = r >> 3, vq = r & 7;
        int gi = ((b * Cc + c) * Tt + t0 + tl) * (Vv / 4) + (v0 >> 2) + vq;
        cat4[c * 32 + r] = x4[gi];
        cat4[(c + 32) * 32 + r] = m4[gi];
    }
    __syncthreads();

    int og = tid >> 5;        // 0..7  (== warp id -> weight loads broadcast)
    int pg = tid & 31;        // 0..31
    float acc[16];
#pragma unroll
    for (int i = 0; i < 16; ++i) acc[i] = 0.f;

#pragma unroll 8
    for (int c = 0; c < 64; ++c) {
        float4 w  = *reinterpret_cast<const float4*>(&wt[c * 32 + (og << 2)]);
        float4 xv = *reinterpret_cast<const float4*>(&cat[c * 128 + (pg << 2)]);
        acc[0]  += w.x * xv.x;  acc[1]  += w.x * xv.y;
        acc[2]  += w.x * xv.z;  acc[3]  += w.x * xv.w;
        acc[4]  += w.y * xv.x;  acc[5]  += w.y * xv.y;
        acc[6]  += w.y * xv.z;  acc[7]  += w.y * xv.w;
        acc[8]  += w.z * xv.x;  acc[9]  += w.z * xv.y;
        acc[10] += w.z * xv.z;  acc[11] += w.z * xv.w;
        acc[12] += w.w * xv.x;  acc[13] += w.w * xv.y;
        acc[14] += w.w * xv.z;  acc[15] += w.w * xv.w;
    }

    // epilogue
    int p0 = pg << 2;              // 4 consecutive p -> same tl, consecutive v
    int tl = p0 >> 5;
    float imp = imps[tl];
    float m0 = 1.f + cvs[p0 + 0];
    float m1 = 1.f + cvs[p0 + 1];
    float m2 = 1.f + cvs[p0 + 2];
    float m3 = 1.f + cvs[p0 + 3];

#pragma unroll
    for (int oo = 0; oo < 4; ++oo) {
        int o = (og << 2) + oo;
        float fbv = fbs[o];
        float4 r;
        r.x = (acc[oo * 4 + 0] + fbv + cat[o * 128 + p0 + 0]) * m0 + imp;
        r.y = (acc[oo * 4 + 1] + fbv + cat[o * 128 + p0 + 1]) * m1 + imp;
        r.z = (acc[oo * 4 + 2] + fbv + cat[o * 128 + p0 + 2]) * m2 + imp;
        r.w = (acc[oo * 4 + 3] + fbv + cat[o * 128 + p0 + 3]) * m3 + imp;
        size_t oi = (size_t)((b * Cc + o) * Tt + t0 + tl) * Vv + v0 + (p0 & 31);
        *reinterpret_cast<float4*>(out + oi) = r;
    }
}

// ---------------------------------------------------------------------------
extern "C" void kernel_launch(void* const* d_in, const int* in_sizes, int n_in,
                              void* d_out, int out_size) {
    const float* flow   = (const float*)d_in[0];
    const float* events = (const float*)d_in[1];
    const float* x      = (const float*)d_in[2];
    const float* ef     = (const float*)d_in[3];
    const float* w1     = (const float*)d_in[4];
    const float* b1     = (const float*)d_in[5];
    const float* w2     = (const float*)d_in[6];
    const float* b2     = (const float*)d_in[7];
    const float* fw     = (const float*)d_in[8];
    const float* fb     = (const float*)d_in[9];
    float* out = (float*)d_out;

    k0_small<<<1, 128>>>(events, ef, w1, b1, w2, b2);
    k_cv<<<8, 256>>>(flow);
    k1_filter<<<(Bc * Cc * Vv) / 128, 128>>>(x);
    k2_mix<<<dim3(Vv / 32, Tt / 4, Bc), 256>>>(x, fw, fb, out);
}

// round 4
// speedup vs baseline: 2.1397x; 2.1397x over previous
#include <cuda_runtime.h>
#include <math.h>

#define Bc 4
#define Tt 288
#define Vv 512
#define Cc 32

// scratch (static __device__ arrays: allowed, no runtime allocation)
__device__ float g_comb[Bc * Cc * Tt * Vv];   // 75.5 MB
__device__ float g_cv[Bc * Tt * Vv];          // 2.36 MB
__device__ float g_imp[Bc * Tt];
__device__ float g_coef[Bc * 5];

// packed fp32x2 FMA (Blackwell FFMA2 — only reachable via PTX)
#define FMA2(acc, a, b) \
    asm("fma.rn.f32x2 %0, %1, %2, %0;" : "+l"(acc) : "l"(a), "l"(b))

__device__ __forceinline__ float2 upk(unsigned long long v) {
    float2 r;
    asm("mov.b64 {%0,%1}, %2;" : "=f"(r.x), "=f"(r.y) : "l"(v));
    return r;
}

// ---------------------------------------------------------------------------
// K0: impact scan (reverse decayed cumsum per (b,e) into private smem columns,
// then parallel reduce over e), plus the event MLP -> coefs. Warp 0 scans,
// warp 1 does the MLP concurrently.
// ---------------------------------------------------------------------------
__global__ void k0_small(const float* __restrict__ events,
                         const float* __restrict__ ef,
                         const float* __restrict__ w1,
                         const float* __restrict__ b1,
                         const float* __restrict__ w2,
                         const float* __restrict__ b2) {
    __shared__ float sev[Bc * Tt * 3];
    __shared__ float part[12 * Tt];
    int tid = threadIdx.x;

    for (int i = tid; i < Bc * Tt * 3; i += blockDim.x) sev[i] = events[i];
    __syncthreads();

    if (tid < 12) {
        int b = tid / 3, e = tid % 3;
        const float decay[3] = {300.f, 600.f, 180.f};
        const float alpha[3] = {0.3f, 0.5f, 0.2f};
        float r = expf(-1.f / decay[e]);
        float a = alpha[e];
        float s = 0.f;
        for (int t = Tt - 1; t >= 0; --t) {
            s = sev[(b * Tt + t) * 3 + e] + r * s;
            part[tid * Tt + t] = a * s;
        }
    }

    if (tid >= 32 && tid < 32 + Bc) {
        int b = tid - 32;
        float h[32];
#pragma unroll
        for (int j = 0; j < 32; ++j) {
            float acc = b1[j];
#pragma unroll
            for (int i = 0; i < 8; ++i) acc += ef[b * 8 + i] * w1[i * 32 + j];
            h[j] = fmaxf(acc, 0.f);
        }
        float lg[5];
#pragma unroll
        for (int k = 0; k < 5; ++k) {
            float acc = b2[k];
#pragma unroll
            for (int j = 0; j < 32; ++j) acc += h[j] * w2[j * 5 + k];
            lg[k] = 1.f / (1.f + expf(-acc));
        }
        float m = lg[0];
#pragma unroll
        for (int k = 1; k < 5; ++k) m = fmaxf(m, lg[k]);
        float ex[5];
        float ssum = 0.f;
#pragma unroll
        for (int k = 0; k < 5; ++k) { ex[k] = expf(lg[k] - m); ssum += ex[k]; }
        const float ks[5] = {3.f, 6.f, 12.f, 24.f, 48.f};
#pragma unroll
        for (int k = 0; k < 5; ++k) g_coef[b * 5 + k] = ex[k] / (ssum * ks[k]);
    }
    __syncthreads();
    for (int i = tid; i < Bc * Tt; i += blockDim.x) {
        int b = i / Tt, t = i - b * Tt;
        g_imp[i] = part[(b * 3 + 0) * Tt + t] +
                   part[(b * 3 + 1) * Tt + t] +
                   part[(b * 3 + 2) * Tt + t];
    }
}

// ---------------------------------------------------------------------------
// Kcv: rolling mean / Bessel std over W=60. Block = (b, 32-v tile), flow tile
// staged in smem; each thread owns (v, 36-t chunk) with a running window,
// seeded by summing the <=60 preceding values. 64 blocks x 256 threads.
// ---------------------------------------------------------------------------
__global__ void __launch_bounds__(256) k_cv(const float* __restrict__ flow) {
    __shared__ float sf[Tt * 32];   // [t][v]
    int tid = threadIdx.x;
    int v0 = blockIdx.x * 32;
    int b = blockIdx.y;

    for (int i = tid; i < Tt * 32; i += 256) {
        int t = i >> 5, v = i & 31;
        sf[i] = flow[(size_t)(b * Tt + t) * Vv + v0 + v];
    }
    __syncthreads();

    int v = tid & 31;
    int ch = tid >> 5;            // 0..7
    int ts = ch * 36;

    float s = 0.f, s2 = 0.f;
    int j0 = ts - 60; if (j0 < 0) j0 = 0;
    for (int j = j0; j < ts; ++j) {
        float f = sf[j * 32 + v];
        s += f; s2 += f * f;
    }
    float* cp = g_cv + (size_t)b * Tt * Vv + v0 + v;
#pragma unroll 4
    for (int t = ts; t < ts + 36; ++t) {
        float f = sf[t * 32 + v];
        s += f; s2 += f * f;
        if (t >= 60) {
            float fo = sf[(t - 60) * 32 + v];
            s -= fo; s2 -= fo * fo;
        }
        float c = 0.f;
        if (t >= 59) {
            float mean = s * (1.f / 60.f);
            float var = (s2 - 60.f * mean * mean) * (1.f / 59.f);
            var = fmaxf(var, 0.f);
            c = sqrtf(var) / (mean + 1e-6f);
        }
        cp[(size_t)t * Vv] = c;
    }
}

// ---------------------------------------------------------------------------
// K1: event-weighted expert filter (unchanged, validated). 5 sliding-window
// sums via a 64-deep smem ring buffer per (b,c,v) column.
// ---------------------------------------------------------------------------
#define SL(i) ((((i) + 64) & 63) * 128 + tid)

__global__ void __launch_bounds__(128) k1_filter(const float* __restrict__ x) {
    __shared__ float rb[64 * 128];
    int tid = threadIdx.x;
    int col = blockIdx.x * 128 + tid;
    int v = col & (Vv - 1);
    int bc = col >> 9;
    int b = bc >> 5;
    const float* xp = x + (size_t)bc * Tt * Vv + v;
    float* cp = g_comb + (size_t)bc * Tt * Vv + v;

    float c0 = g_coef[b * 5 + 0];
    float c1 = g_coef[b * 5 + 1];
    float c2 = g_coef[b * 5 + 2];
    float c3 = g_coef[b * 5 + 3];
    float c4 = g_coef[b * 5 + 4];

#pragma unroll
    for (int s = 0; s < 64; ++s) rb[s * 128 + tid] = 0.f;

    float S0 = 0.f, S1 = 0.f, S2 = 0.f, S3 = 0.f, S4 = 0.f;

#pragma unroll 4
    for (int t = -24; t < Tt; ++t) {
        float a3  = rb[SL(t + 1)];
        float a6  = rb[SL(t + 2)];
        float a12 = rb[SL(t + 5)];
        float a24 = rb[SL(t + 11)];
        float d3  = rb[SL(t - 2)];
        float d6  = rb[SL(t - 4)];
        float d12 = rb[SL(t - 7)];
        float d24 = rb[SL(t - 13)];
        float d48 = rb[SL(t - 25)];

        int tin = t + 23;
        float xin = 0.f;
        if ((unsigned)tin < (unsigned)Tt) xin = __ldg(xp + (size_t)tin * Vv);

        S0 += a3  - d3;
        S1 += a6  - d6;
        S2 += a12 - d12;
        S3 += a24 - d24;
        S4 += xin - d48;

        rb[SL(tin)] = xin;

        if (t >= 0) {
            cp[(size_t)t * Vv] =
                c0 * S0 + c1 * S1 + c2 * S2 + c3 * S3 + c4 * S4;
        }
    }
}

// ---------------------------------------------------------------------------
// K2: fused channel mix + residual + CV + impact, FFMA2 version.
// Block: one b, one t, 128 v, all 32 o. Thread tile 8o x 4p (as 2 f32x2
// pairs). Weights stored DUPLICATED as float2 in smem so both FFMA2 operands
// arrive pre-packed from LDS.128 — zero pack instructions in the inner loop.
// Per c per thread: 1 cat LDS.128 + 4 broadcast weight LDS.128 + 16 FFMA2.
// ---------------------------------------------------------------------------
__global__ void __launch_bounds__(128) k2_mix(const float* __restrict__ x,
                                              const float* __restrict__ fw,
                                              const float* __restrict__ fb,
                                              float* __restrict__ out) {
    __shared__ __align__(16) float  s_cat[64 * 128];   // 32 KB  [c][p]
    __shared__ __align__(16) float2 s_wd[64 * 32];     // 16 KB  [c][o] dup pairs

    int tid = threadIdx.x;
    int v0 = blockIdx.x * 128;
    int t0 = blockIdx.y;
    int b  = blockIdx.z;

    // fill cat tile: rows 0..31 = x, rows 32..63 = comb (float4, coalesced)
    const float4* x4 = reinterpret_cast<const float4*>(x);
    const float4* m4 = reinterpret_cast<const float4*>(g_comb);
    float4* cat4 = reinterpret_cast<float4*>(s_cat);
#pragma unroll
    for (int k = 0; k < 8; ++k) {
        int i = tid + k * 128;            // 0..1023
        int c = i >> 5, r = i & 31;
        int gi = ((b * Cc + c) * Tt + t0) * (Vv / 4) + (v0 >> 2) + r;
        cat4[c * 32 + r] = x4[gi];
        cat4[(c + 32) * 32 + r] = m4[gi];
    }
    // fill duplicated weights: s_wd[c][o] = (w[o][c], w[o][c])
#pragma unroll
    for (int k = 0; k < 16; ++k) {
        int i = tid + k * 128;            // 0..2047
        int o = i & 31, c = i >> 5;
        float w = fw[o * 64 + c];
        s_wd[c * 32 + o] = make_float2(w, w);
    }
    __syncthreads();

    int og = tid >> 5;                    // 0..3  -> o = og*8 .. og*8+7
    int pg = tid & 31;                    // 0..31 -> p = pg*4 .. pg*4+3
    int p0 = pg << 2;

    unsigned long long acc[8][2];
#pragma unroll
    for (int oo = 0; oo < 8; ++oo) { acc[oo][0] = 0ull; acc[oo][1] = 0ull; }

    const ulonglong2* wbase =
        reinterpret_cast<const ulonglong2*>(s_wd) + og * 4;   // 4 ull2 = 8 dup-pairs

#pragma unroll 8
    for (int c = 0; c < 64; ++c) {
        ulonglong2 xv =
            *reinterpret_cast<const ulonglong2*>(&s_cat[c * 128 + p0]);
        const ulonglong2* wr = wbase + c * 16;
        ulonglong2 w01 = wr[0];
        ulonglong2 w23 = wr[1];
        ulonglong2 w45 = wr[2];
        ulonglong2 w67 = wr[3];
        FMA2(acc[0][0], w01.x, xv.x); FMA2(acc[0][1], w01.x, xv.y);
        FMA2(acc[1][0], w01.y, xv.x); FMA2(acc[1][1], w01.y, xv.y);
        FMA2(acc[2][0], w23.x, xv.x); FMA2(acc[2][1], w23.x, xv.y);
        FMA2(acc[3][0], w23.y, xv.x); FMA2(acc[3][1], w23.y, xv.y);
        FMA2(acc[4][0], w45.x, xv.x); FMA2(acc[4][1], w45.x, xv.y);
        FMA2(acc[5][0], w45.y, xv.x); FMA2(acc[5][1], w45.y, xv.y);
        FMA2(acc[6][0], w67.x, xv.x); FMA2(acc[6][1], w67.x, xv.y);
        FMA2(acc[7][0], w67.y, xv.x); FMA2(acc[7][1], w67.y, xv.y);
    }

    // epilogue: residual (x half of cat) + bias, * (1+cv), + impact
    float4 cvv = *reinterpret_cast<const float4*>(
        g_cv + (size_t)(b * Tt + t0) * Vv + v0 + p0);
    float m0 = 1.f + cvv.x, m1 = 1.f + cvv.y;
    float m2 = 1.f + cvv.z, m3 = 1.f + cvv.w;
    float imp = g_imp[b * Tt + t0];

#pragma unroll
    for (int oo = 0; oo < 8; ++oo) {
        int o = (og << 3) + oo;
        float2 lo = upk(acc[oo][0]);
        float2 hi = upk(acc[oo][1]);
        float fbv = __ldg(fb + o);
        float4 xres = *reinterpret_cast<const float4*>(&s_cat[o * 128 + p0]);
        float4 r;
        r.x = (lo.x + fbv + xres.x) * m0 + imp;
        r.y = (lo.y + fbv + xres.y) * m1 + imp;
        r.z = (hi.x + fbv + xres.z) * m2 + imp;
        r.w = (hi.y + fbv + xres.w) * m3 + imp;
        size_t oi = ((size_t)(b * Cc + o) * Tt + t0) * Vv + v0 + p0;
        *reinterpret_cast<float4*>(out + oi) = r;
    }
}

// ---------------------------------------------------------------------------
extern "C" void kernel_launch(void* const* d_in, const int* in_sizes, int n_in,
                              void* d_out, int out_size) {
    const float* flow   = (const float*)d_in[0];
    const float* events = (const float*)d_in[1];
    const float* x      = (const float*)d_in[2];
    const float* ef     = (const float*)d_in[3];
    const float* w1     = (const float*)d_in[4];
    const float* b1     = (const float*)d_in[5];
    const float* w2     = (const float*)d_in[6];
    const float* b2     = (const float*)d_in[7];
    const float* fw     = (const float*)d_in[8];
    const float* fb     = (const float*)d_in[9];
    float* out = (float*)d_out;

    k0_small<<<1, 128>>>(events, ef, w1, b1, w2, b2);
    k_cv<<<dim3(Vv / 32, Bc), 256>>>(flow);
    k1_filter<<<(Bc * Cc * Vv) / 128, 128>>>(x);
    k2_mix<<<dim3(Vv / 128, Tt, Bc), 128>>>(x, fw, fb, out);
}